// round 3
// baseline (speedup 1.0000x reference)
#include <cuda_runtime.h>
#include <cuda_bf16.h>

// ---------------------------------------------------------------------------
// Quanv3x3 quantum-patch layer, 9-qubit statevector sim.
//
// Sim count: B(8) * C(4) * 28 * 28 = 25088. One warp per simulation.
// State: 512 complex amps = 16 complex per lane, in registers.
//
// Global amplitude index bit layout (bit b of idx, qubit q -> bit 8-q in ref):
//   lane bit 0 -> qubit 8      local bit 0 -> qubit 7
//   lane bit 1 -> qubit 5      local bit 1 -> qubit 6
//   lane bit 2 -> qubit 3      local bit 2 -> qubit 4
//   lane bit 3 -> qubit 1      local bit 3 -> qubit 0
//   lane bit 4 -> qubit 2
// Chosen so only CRX on pair (3,2) is cross-lane (32 shfl/thread/sim total).
// ---------------------------------------------------------------------------

#define FULLMASK 0xffffffffu

__device__ float g_avg[7200];   // (8,30,30) channel-mean image
__device__ float g_gc[64];      // cos(theta/2) per channel (4x16)
__device__ float g_gs[64];      // sin(theta/2) per channel

__global__ void prep_kernel(const float* __restrict__ x,
                            const float* __restrict__ qp,
                            float* __restrict__ out) {
    int i = blockIdx.x * blockDim.x + threadIdx.x;
    if (i < 28800) out[i] = 0.0f;                // zero padded output
    if (i < 7200) {
        const float* p = x + i * 3;
        g_avg[i] = (p[0] + p[1] + p[2]) * (1.0f / 3.0f);
    }
    if (i < 64) {
        float h = qp[i] * 0.5f;
        g_gc[i] = cosf(h);
        g_gs[i] = sinf(h);
    }
}

// CRZ, control = uniform-per-lane predicate, target = local bit TB.
template <int TB>
__device__ __forceinline__ void crz_lanectl(float (&re)[16], float (&im)[16],
                                            bool ctl, float ch, float sh) {
    if (ctl) {
#pragma unroll
        for (int li = 0; li < 16; li++) {
            float se = (li & TB) ? sh : -sh;
            float nr = re[li] * ch - im[li] * se;
            float ni = im[li] * ch + re[li] * se;
            re[li] = nr; im[li] = ni;
        }
    }
}

// CRX, control = uniform-per-lane predicate, target = local bit TB.
template <int TB>
__device__ __forceinline__ void crx_lanectl(float (&re)[16], float (&im)[16],
                                            bool ctl, float ch, float sh) {
    if (ctl) {
#pragma unroll
        for (int li = 0; li < 16; li++) {
            if (!(li & TB)) {
                int lj = li | TB;
                float ar = re[li], ai = im[li];
                float br = re[lj], bi = im[lj];
                re[li] = ch * ar + sh * bi;
                im[li] = ch * ai - sh * br;
                re[lj] = ch * br + sh * ai;
                im[lj] = ch * bi - sh * ar;
            }
        }
    }
}

// CRZ, control = local bit CB, target = local bit TB (fully local).
template <int CB, int TB>
__device__ __forceinline__ void crz_local(float (&re)[16], float (&im)[16],
                                          float ch, float sh) {
#pragma unroll
    for (int li = 0; li < 16; li++) {
        if (li & CB) {
            float se = (li & TB) ? sh : -sh;
            float nr = re[li] * ch - im[li] * se;
            float ni = im[li] * ch + re[li] * se;
            re[li] = nr; im[li] = ni;
        }
    }
}

// CRX, control = local bit CB, target = local bit TB (fully local).
template <int CB, int TB>
__device__ __forceinline__ void crx_local(float (&re)[16], float (&im)[16],
                                          float ch, float sh) {
#pragma unroll
    for (int li = 0; li < 16; li++) {
        if ((li & CB) && !(li & TB)) {
            int lj = li | TB;
            float ar = re[li], ai = im[li];
            float br = re[lj], bi = im[lj];
            re[li] = ch * ar + sh * bi;
            im[li] = ch * ai - sh * br;
            re[lj] = ch * br + sh * ai;
            im[lj] = ch * bi - sh * ar;
        }
    }
}

__global__ __launch_bounds__(256, 2) void sim_kernel(float* __restrict__ out) {
    int gwarp = (blockIdx.x * blockDim.x + threadIdx.x) >> 5;
    int lane = threadIdx.x & 31;
    if (gwarp >= 25088) return;

    int b   = gwarp / 3136;
    int rem = gwarp - b * 3136;
    int ch  = rem / 784;
    int pos = rem - ch * 784;
    int r   = pos / 28;
    int c   = pos - r * 28;

    // ---- patch angles: c_q = sin(pi*p), s_q = -cos(pi*p)  (h = pi*p - pi/2)
    float sv = 0.0f, cv = 0.0f;
    if (lane < 9) {
        int dr = lane / 3;
        int dc = lane - dr * 3;
        float p = g_avg[b * 900 + (r + dr) * 30 + (c + dc)];
        sincosf(3.14159265358979323846f * p, &sv, &cv);
    }
    float cq[9], sq[9];
#pragma unroll
    for (int q = 0; q < 9; q++) {
        cq[q] = __shfl_sync(FULLMASK, sv, q);
        sq[q] = -__shfl_sync(FULLMASK, cv, q);
    }

    // ---- initial product state: amp = r * (-i)^popcount(idx)
    float lr = ((lane & 1)  ? sq[8] : cq[8]) *
               ((lane & 2)  ? sq[5] : cq[5]) *
               ((lane & 4)  ? sq[3] : cq[3]) *
               ((lane & 8)  ? sq[1] : cq[1]) *
               ((lane & 16) ? sq[2] : cq[2]);
    int lk = __popc(lane & 31);

    float re[16], im[16];
#pragma unroll
    for (int li = 0; li < 16; li++) {
        float rr = lr * ((li & 1) ? sq[7] : cq[7]) *
                        ((li & 2) ? sq[6] : cq[6]) *
                        ((li & 4) ? sq[4] : cq[4]) *
                        ((li & 8) ? sq[0] : cq[0]);
        int k = (lk + __popc(li)) & 3;
        re[li] = (k == 0) ? rr : ((k == 2) ? -rr : 0.0f);
        im[li] = (k == 1) ? -rr : ((k == 3) ? rr : 0.0f);
    }

    const float* gc = g_gc + ch * 16;
    const float* gs = g_gs + ch * 16;

    // ---- gate 0: pair (1,0). ctrl = lane bit 8 (q1), tgt = local bit 8 (q0)
    {
        float cz = __ldg(gc + 0), sz = __ldg(gs + 0);
        float cx = __ldg(gc + 1), sx = __ldg(gs + 1);
        bool ctl = (lane & 8) != 0;
        crz_lanectl<8>(re, im, ctl, cz, sz);
        crx_lanectl<8>(re, im, ctl, cx, sx);
    }
    // ---- gate 1: pair (3,2). ctrl = lane bit 4 (q3), tgt = lane bit 16 (q2)
    {
        float cz = __ldg(gc + 2), sz = __ldg(gs + 2);
        float cx = __ldg(gc + 3), sx = __ldg(gs + 3);
        bool ctl = (lane & 4) != 0;
        if (ctl) {
            float se = (lane & 16) ? sz : -sz;
#pragma unroll
            for (int li = 0; li < 16; li++) {
                float nr = re[li] * cz - im[li] * se;
                float ni = im[li] * cz + re[li] * se;
                re[li] = nr; im[li] = ni;
            }
        }
        // CRX cross-lane: partner lane ^ 16; RX off-diagonal symmetric so
        // both sides use new = c*mine - i*s*other.
#pragma unroll
        for (int li = 0; li < 16; li++) {
            float orr = __shfl_xor_sync(FULLMASK, re[li], 16);
            float oii = __shfl_xor_sync(FULLMASK, im[li], 16);
            if (ctl) {
                float nr = cx * re[li] + sx * oii;
                float ni = cx * im[li] - sx * orr;
                re[li] = nr; im[li] = ni;
            }
        }
    }
    // ---- gate 2: pair (2,0). ctrl = lane bit 16 (q2), tgt = local bit 8 (q0)
    {
        float cz = __ldg(gc + 4), sz = __ldg(gs + 4);
        float cx = __ldg(gc + 5), sx = __ldg(gs + 5);
        bool ctl = (lane & 16) != 0;
        crz_lanectl<8>(re, im, ctl, cz, sz);
        crx_lanectl<8>(re, im, ctl, cx, sx);
    }
    // ---- gate 3: pair (8,7). ctrl = lane bit 1 (q8), tgt = local bit 1 (q7)
    {
        float cz = __ldg(gc + 6), sz = __ldg(gs + 6);
        float cx = __ldg(gc + 7), sx = __ldg(gs + 7);
        bool ctl = (lane & 1) != 0;
        crz_lanectl<1>(re, im, ctl, cz, sz);
        crx_lanectl<1>(re, im, ctl, cx, sx);
    }
    // ---- gate 4: pair (5,4). ctrl = lane bit 2 (q5), tgt = local bit 4 (q4)
    {
        float cz = __ldg(gc + 8), sz = __ldg(gs + 8);
        float cx = __ldg(gc + 9), sx = __ldg(gs + 9);
        bool ctl = (lane & 2) != 0;
        crz_lanectl<4>(re, im, ctl, cz, sz);
        crx_lanectl<4>(re, im, ctl, cx, sx);
    }
    // ---- gate 5: pair (7,6). ctrl = local bit 1 (q7), tgt = local bit 2 (q6)
    {
        float cz = __ldg(gc + 10), sz = __ldg(gs + 10);
        float cx = __ldg(gc + 11), sx = __ldg(gs + 11);
        crz_local<1, 2>(re, im, cz, sz);
        crx_local<1, 2>(re, im, cx, sx);
    }
    // ---- gate 6: pair (6,4). ctrl = local bit 2 (q6), tgt = local bit 4 (q4)
    {
        float cz = __ldg(gc + 12), sz = __ldg(gs + 12);
        float cx = __ldg(gc + 13), sx = __ldg(gs + 13);
        crz_local<2, 4>(re, im, cz, sz);
        crx_local<2, 4>(re, im, cx, sx);
    }
    // ---- gate 7: pair (4,0). ctrl = local bit 4 (q4), tgt = local bit 8 (q0)
    {
        float cz = __ldg(gc + 14), sz = __ldg(gs + 14);
        float cx = __ldg(gc + 15), sx = __ldg(gs + 15);
        crz_local<4, 8>(re, im, cz, sz);
        crx_local<4, 8>(re, im, cx, sx);
    }

    // ---- measurement: z = sum_{q0=0} |amp|^2 - sum_{q0=1} |amp|^2
    float z = 0.0f;
#pragma unroll
    for (int li = 0; li < 16; li++) {
        float p = re[li] * re[li] + im[li] * im[li];
        z += (li & 8) ? -p : p;
    }
#pragma unroll
    for (int o = 16; o > 0; o >>= 1)
        z += __shfl_xor_sync(FULLMASK, z, o);

    if (lane == 0) {
        // feat (b,ch,r,c) -> out[b, r+1, c+1, ch] with 30x30 padded HW
        out[((b * 30 + r + 1) * 30 + (c + 1)) * 4 + ch] = (z + 1.0f) * 0.5f;
    }
}

extern "C" void kernel_launch(void* const* d_in, const int* in_sizes, int n_in,
                              void* d_out, int out_size) {
    const float* x  = (const float*)d_in[0];
    const float* qp = (const float*)d_in[1];
    if (n_in >= 2 && in_sizes[0] == 64) {  // defensive: metadata order swap
        const float* t = x; x = qp; qp = t;
    }
    float* out = (float*)d_out;

    prep_kernel<<<(28800 + 255) / 256, 256>>>(x, qp, out);
    sim_kernel<<<3136, 256>>>(out);
}

// round 4
// speedup vs baseline: 1.5004x; 1.5004x over previous
#include <cuda_runtime.h>
#include <cuda_bf16.h>

// ---------------------------------------------------------------------------
// Quanv3x3 9-qubit statevector sim, packed-f32x2 edition.
//
// One warp per sim (25088 sims). 512 amps = 16 complex/lane, stored as
// 8 x f32x2 packed pairs (pair dimension = qubit 7).
//
// Amp index bits:  lane b0=q8  b1=q5  b2=q3  b3=q1  b4=q2
//                  pair-lo/hi = q7;  k b0=q6  k b1=q4  k b2=q0
// Only CRX of pair (3,2) crosses lanes (xor 16). All controlled gates use
// constant-folded controls (identity rotation on off lanes) -> no divergence.
// ---------------------------------------------------------------------------

#define FULLMASK 0xffffffffu
typedef unsigned long long u64;

__device__ float g_avg[7200];   // (8,30,30) channel-mean image
__device__ float g_gc[64];      // cos(theta/2) per channel (4x16)
__device__ float g_gs[64];      // sin(theta/2)

__global__ void prep_kernel(const float* __restrict__ x,
                            const float* __restrict__ qp,
                            float* __restrict__ out) {
    int i = blockIdx.x * blockDim.x + threadIdx.x;
    if (i < 28800) out[i] = 0.0f;
    if (i < 7200) {
        const float* p = x + i * 3;
        g_avg[i] = (p[0] + p[1] + p[2]) * (1.0f / 3.0f);
    }
    if (i < 64) {
        float h = qp[i] * 0.5f;
        g_gc[i] = cosf(h);
        g_gs[i] = sinf(h);
    }
}

// ---- packed f32x2 primitives ----------------------------------------------
__device__ __forceinline__ u64 pk(float lo, float hi) {
    u64 r;
    asm("mov.b64 %0, {%1, %2};" : "=l"(r) : "f"(lo), "f"(hi));
    return r;
}
__device__ __forceinline__ void upk(u64 v, float& lo, float& hi) {
    asm("mov.b64 {%0, %1}, %2;" : "=f"(lo), "=f"(hi) : "l"(v));
}
__device__ __forceinline__ u64 f2fma(u64 a, u64 b, u64 c) {
    u64 d;
    asm("fma.rn.f32x2 %0, %1, %2, %3;" : "=l"(d) : "l"(a), "l"(b), "l"(c));
    return d;
}
__device__ __forceinline__ u64 f2mul(u64 a, u64 b) {
    u64 d;
    asm("mul.rn.f32x2 %0, %1, %2;" : "=l"(d) : "l"(a), "l"(b));
    return d;
}
__device__ __forceinline__ u64 f2swap(u64 v) {
    float lo, hi; upk(v, lo, hi); return pk(hi, lo);
}

// CRZ on one packed pair: (r,i) *= exp(i*se*Z-ish); nr = ch*r - se*i, ni = ch*i + se*r
// se2 = packed +se per slot, mse2 = packed -se per slot.
__device__ __forceinline__ void crz1(u64& r, u64& i, u64 ch2, u64 se2, u64 mse2) {
    u64 tr = f2mul(mse2, i);
    u64 ti = f2mul(se2, r);
    r = f2fma(ch2, r, tr);
    i = f2fma(ch2, i, ti);
}

// CRX mixing packed pair A (target bit 0) with packed pair B (target bit 1).
__device__ __forceinline__ void crx2(u64& rA, u64& iA, u64& rB, u64& iB,
                                     u64 ch2, u64 sh2, u64 msh2) {
    u64 m0 = f2mul(sh2,  iB);
    u64 m1 = f2mul(msh2, rB);
    u64 m2 = f2mul(sh2,  iA);
    u64 m3 = f2mul(msh2, rA);
    rA = f2fma(ch2, rA, m0);
    iA = f2fma(ch2, iA, m1);
    rB = f2fma(ch2, rB, m2);
    iB = f2fma(ch2, iB, m3);
}

__global__ __launch_bounds__(256, 2) void sim_kernel(float* __restrict__ out) {
    int gwarp = (blockIdx.x * blockDim.x + threadIdx.x) >> 5;
    int lane = threadIdx.x & 31;
    if (gwarp >= 25088) return;

    int b   = gwarp / 3136;
    int rem = gwarp - b * 3136;
    int ch  = rem / 784;
    int pos = rem - ch * 784;
    int r_  = pos / 28;
    int c_  = pos - r_ * 28;

    // ---- patch angles: cq = sin(pi*p), sq = -cos(pi*p)
    float sv = 0.0f, cv = 0.0f;
    if (lane < 9) {
        int dr = lane / 3;
        int dc = lane - dr * 3;
        float p = g_avg[b * 900 + (r_ + dr) * 30 + (c_ + dc)];
        sincosf(3.14159265358979323846f * p, &sv, &cv);
    }
    float cq[9], sq[9];
#pragma unroll
    for (int q = 0; q < 9; q++) {
        cq[q] = __shfl_sync(FULLMASK, sv, q);
        sq[q] = -__shfl_sync(FULLMASK, cv, q);
    }

    // ---- initial product state: amp(idx) = rr * (-i)^popcount(idx)
    float lr = ((lane & 1)  ? sq[8] : cq[8]) *
               ((lane & 2)  ? sq[5] : cq[5]) *
               ((lane & 4)  ? sq[3] : cq[3]) *
               ((lane & 8)  ? sq[1] : cq[1]) *
               ((lane & 16) ? sq[2] : cq[2]);
    int lk = __popc(lane & 31) & 3;
    // w = (-i)^lk
    float wr = (lk == 0) ? 1.0f : ((lk == 2) ? -1.0f : 0.0f);
    float wi = (lk == 3) ? 1.0f : ((lk == 1) ? -1.0f : 0.0f);

    u64 re[8], im[8];
#pragma unroll
    for (int k = 0; k < 8; k++) {
        float rr = lr * ((k & 1) ? sq[6] : cq[6]) *
                        ((k & 2) ? sq[4] : cq[4]) *
                        ((k & 4) ? sq[0] : cq[0]);
        int p = __popc(k) & 3;  // compile-time under unroll
        float wkr = (p == 0) ? wr : (p == 1) ? wi : (p == 2) ? -wr : -wi;
        float wki = (p == 0) ? wi : (p == 1) ? -wr : (p == 2) ? -wi : wr;
        float t1 = rr * cq[7], t2 = rr * sq[7];
        re[k] = pk(t1 * wkr,  t2 * wki);
        im[k] = pk(t1 * wki, -(t2 * wkr));
    }

    const float* gc = g_gc + ch * 16;
    const float* gs = g_gs + ch * 16;

    // ---- gate 0: (1,0). ctl = lane&8; CRZ sign by k&4; CRX pairs k^4
    {
        bool ctl = (lane & 8) != 0;
        float c = __ldg(gc + 0), s = __ldg(gs + 0);
        float ce = ctl ? c : 1.0f, se = ctl ? s : 0.0f;
        u64 ch2 = pk(ce, ce), sP = pk(se, se), sN = pk(-se, -se);
#pragma unroll
        for (int k = 0; k < 8; k++)
            crz1(re[k], im[k], ch2, (k & 4) ? sP : sN, (k & 4) ? sN : sP);
        float cx = __ldg(gc + 1), sx = __ldg(gs + 1);
        float cxe = ctl ? cx : 1.0f, sxe = ctl ? sx : 0.0f;
        u64 cx2 = pk(cxe, cxe), x2P = pk(sxe, sxe), x2N = pk(-sxe, -sxe);
        crx2(re[0], im[0], re[4], im[4], cx2, x2P, x2N);
        crx2(re[1], im[1], re[5], im[5], cx2, x2P, x2N);
        crx2(re[2], im[2], re[6], im[6], cx2, x2P, x2N);
        crx2(re[3], im[3], re[7], im[7], cx2, x2P, x2N);
    }
    // ---- gate 1: (3,2). ctl = lane&4; CRZ sign by lane&16; CRX cross-lane xor16
    {
        bool ctl = (lane & 4) != 0;
        float c = __ldg(gc + 2), s = __ldg(gs + 2);
        float sgn = (lane & 16) ? s : -s;
        float ce = ctl ? c : 1.0f, se = ctl ? sgn : 0.0f;
        u64 ch2 = pk(ce, ce), sP = pk(se, se), sN = pk(-se, -se);
#pragma unroll
        for (int k = 0; k < 8; k++)
            crz1(re[k], im[k], ch2, sP, sN);
        float cx = __ldg(gc + 3), sx = __ldg(gs + 3);
        float cxe = ctl ? cx : 1.0f, sxe = ctl ? sx : 0.0f;
        u64 cx2 = pk(cxe, cxe), x2P = pk(sxe, sxe), x2N = pk(-sxe, -sxe);
#pragma unroll
        for (int k = 0; k < 8; k++) {
            u64 orr = __shfl_xor_sync(FULLMASK, re[k], 16);
            u64 oii = __shfl_xor_sync(FULLMASK, im[k], 16);
            u64 m0 = f2mul(x2P, oii);
            u64 m1 = f2mul(x2N, orr);
            re[k] = f2fma(cx2, re[k], m0);
            im[k] = f2fma(cx2, im[k], m1);
        }
    }
    // ---- gate 2: (2,0). ctl = lane&16; same shape as gate 0
    {
        bool ctl = (lane & 16) != 0;
        float c = __ldg(gc + 4), s = __ldg(gs + 4);
        float ce = ctl ? c : 1.0f, se = ctl ? s : 0.0f;
        u64 ch2 = pk(ce, ce), sP = pk(se, se), sN = pk(-se, -se);
#pragma unroll
        for (int k = 0; k < 8; k++)
            crz1(re[k], im[k], ch2, (k & 4) ? sP : sN, (k & 4) ? sN : sP);
        float cx = __ldg(gc + 5), sx = __ldg(gs + 5);
        float cxe = ctl ? cx : 1.0f, sxe = ctl ? sx : 0.0f;
        u64 cx2 = pk(cxe, cxe), x2P = pk(sxe, sxe), x2N = pk(-sxe, -sxe);
        crx2(re[0], im[0], re[4], im[4], cx2, x2P, x2N);
        crx2(re[1], im[1], re[5], im[5], cx2, x2P, x2N);
        crx2(re[2], im[2], re[6], im[6], cx2, x2P, x2N);
        crx2(re[3], im[3], re[7], im[7], cx2, x2P, x2N);
    }
    // ---- gate 3: (8,7). ctl = lane&1; target = within-pair bit (q7)
    {
        bool ctl = (lane & 1) != 0;
        float c = __ldg(gc + 6), s = __ldg(gs + 6);
        float ce = ctl ? c : 1.0f, se = ctl ? s : 0.0f;
        u64 ch2 = pk(ce, ce), se2 = pk(-se, se), mse2 = pk(se, -se);
#pragma unroll
        for (int k = 0; k < 8; k++)
            crz1(re[k], im[k], ch2, se2, mse2);
        float cx = __ldg(gc + 7), sx = __ldg(gs + 7);
        float cxe = ctl ? cx : 1.0f, sxe = ctl ? sx : 0.0f;
        u64 cx2 = pk(cxe, cxe), x2P = pk(sxe, sxe), x2N = pk(-sxe, -sxe);
#pragma unroll
        for (int k = 0; k < 8; k++) {
            u64 swi = f2swap(im[k]);
            u64 swr = f2swap(re[k]);
            u64 m0 = f2mul(x2P, swi);
            u64 m1 = f2mul(x2N, swr);
            re[k] = f2fma(cx2, re[k], m0);
            im[k] = f2fma(cx2, im[k], m1);
        }
    }
    // ---- gate 4: (5,4). ctl = lane&2; CRZ sign by k&2; CRX pairs k^2
    {
        bool ctl = (lane & 2) != 0;
        float c = __ldg(gc + 8), s = __ldg(gs + 8);
        float ce = ctl ? c : 1.0f, se = ctl ? s : 0.0f;
        u64 ch2 = pk(ce, ce), sP = pk(se, se), sN = pk(-se, -se);
#pragma unroll
        for (int k = 0; k < 8; k++)
            crz1(re[k], im[k], ch2, (k & 2) ? sP : sN, (k & 2) ? sN : sP);
        float cx = __ldg(gc + 9), sx = __ldg(gs + 9);
        float cxe = ctl ? cx : 1.0f, sxe = ctl ? sx : 0.0f;
        u64 cx2 = pk(cxe, cxe), x2P = pk(sxe, sxe), x2N = pk(-sxe, -sxe);
        crx2(re[0], im[0], re[2], im[2], cx2, x2P, x2N);
        crx2(re[1], im[1], re[3], im[3], cx2, x2P, x2N);
        crx2(re[4], im[4], re[6], im[6], cx2, x2P, x2N);
        crx2(re[5], im[5], re[7], im[7], cx2, x2P, x2N);
    }
    // ---- gate 5: (7,6). ctl = within-pair hi (q7); tgt = k bit0 (q6)
    {
        float c = __ldg(gc + 10), s = __ldg(gs + 10);
        u64 ch2 = pk(1.0f, c), sP = pk(0.0f, s), sN = pk(0.0f, -s);
#pragma unroll
        for (int k = 0; k < 8; k++)
            crz1(re[k], im[k], ch2, (k & 1) ? sP : sN, (k & 1) ? sN : sP);
        float cx = __ldg(gc + 11), sx = __ldg(gs + 11);
        u64 cx2 = pk(1.0f, cx), x2P = pk(0.0f, sx), x2N = pk(0.0f, -sx);
        crx2(re[0], im[0], re[1], im[1], cx2, x2P, x2N);
        crx2(re[2], im[2], re[3], im[3], cx2, x2P, x2N);
        crx2(re[4], im[4], re[5], im[5], cx2, x2P, x2N);
        crx2(re[6], im[6], re[7], im[7], cx2, x2P, x2N);
    }
    // ---- gate 6: (6,4). ctl = k&1 (q6); tgt = k bit1 (q4); sign by k&2
    {
        float c = __ldg(gc + 12), s = __ldg(gs + 12);
        u64 ch2 = pk(c, c), sP = pk(s, s), sN = pk(-s, -s);
        crz1(re[1], im[1], ch2, sN, sP);
        crz1(re[3], im[3], ch2, sP, sN);
        crz1(re[5], im[5], ch2, sN, sP);
        crz1(re[7], im[7], ch2, sP, sN);
        float cx = __ldg(gc + 13), sx = __ldg(gs + 13);
        u64 cx2 = pk(cx, cx), x2P = pk(sx, sx), x2N = pk(-sx, -sx);
        crx2(re[1], im[1], re[3], im[3], cx2, x2P, x2N);
        crx2(re[5], im[5], re[7], im[7], cx2, x2P, x2N);
    }
    // ---- gate 7: (4,0). ctl = k&2 (q4); tgt = k bit2 (q0); sign by k&4
    {
        float c = __ldg(gc + 14), s = __ldg(gs + 14);
        u64 ch2 = pk(c, c), sP = pk(s, s), sN = pk(-s, -s);
        crz1(re[2], im[2], ch2, sN, sP);
        crz1(re[3], im[3], ch2, sN, sP);
        crz1(re[6], im[6], ch2, sP, sN);
        crz1(re[7], im[7], ch2, sP, sN);
        float cx = __ldg(gc + 15), sx = __ldg(gs + 15);
        u64 cx2 = pk(cx, cx), x2P = pk(sx, sx), x2N = pk(-sx, -sx);
        crx2(re[2], im[2], re[6], im[6], cx2, x2P, x2N);
        crx2(re[3], im[3], re[7], im[7], cx2, x2P, x2N);
    }

    // ---- measurement: z = P(q0=0) - P(q0=1); q0 = k bit2
    u64 accP = 0ULL, accN = 0ULL;   // bit pattern 0 == (0.f, 0.f)
#pragma unroll
    for (int k = 0; k < 8; k++) {
        if (k < 4) {
            accP = f2fma(re[k], re[k], accP);
            accP = f2fma(im[k], im[k], accP);
        } else {
            accN = f2fma(re[k], re[k], accN);
            accN = f2fma(im[k], im[k], accN);
        }
    }
    float pl, ph, nl, nh;
    upk(accP, pl, ph);
    upk(accN, nl, nh);
    float z = (pl + ph) - (nl + nh);
#pragma unroll
    for (int o = 16; o > 0; o >>= 1)
        z += __shfl_xor_sync(FULLMASK, z, o);

    if (lane == 0) {
        out[((b * 30 + r_ + 1) * 30 + (c_ + 1)) * 4 + ch] = (z + 1.0f) * 0.5f;
    }
}

extern "C" void kernel_launch(void* const* d_in, const int* in_sizes, int n_in,
                              void* d_out, int out_size) {
    const float* x  = (const float*)d_in[0];
    const float* qp = (const float*)d_in[1];
    if (n_in >= 2 && in_sizes[0] == 64) {
        const float* t = x; x = qp; qp = t;
    }
    float* out = (float*)d_out;

    prep_kernel<<<(28800 + 255) / 256, 256>>>(x, qp, out);
    sim_kernel<<<3136, 256>>>(out);
}